// round 3
// baseline (speedup 1.0000x reference)
#include <cuda_runtime.h>

#define TSEQ  512
#define BATCH 128
#define HID   1024
#define NLAY  4
#define BH    (BATCH*HID)

#define MR 64      // M tile (batch rows)
#define NR 64      // N tile (output cols)
#define KB 32      // K chunk

// Ring buffers for hidden state of layers 0..2 (layer 3 lives in d_out). 3 MB.
__device__ float g_hbuf[3*2*BH];

// Packed dual-FMA: sm_103a FFMA2 (2x FFMA throughput), only reachable via PTX.
__device__ __forceinline__ void fma2(unsigned long long& c,
                                     unsigned long long a,
                                     unsigned long long b) {
    asm("fma.rn.f32x2 %0, %1, %2, %0;" : "+l"(c) : "l"(a), "l"(b));
}

__device__ __forceinline__ void cp_async16(unsigned smem_addr, const void* gptr) {
    asm volatile("cp.async.ca.shared.global [%0], [%1], 16;\n"
                 :: "r"(smem_addr), "l"(gptr));
}
__device__ __forceinline__ void cp_commit() {
    asm volatile("cp.async.commit_group;\n" ::: "memory");
}
template<int N>
__device__ __forceinline__ void cp_wait() {
    asm volatile("cp.async.wait_group %0;\n" :: "n"(N) : "memory");
}

// Swizzled float index for a 64x32 tile stored as 32 floats/row:
// 16B granule g (0..7) XORed with row&7 -> conflict-free per-lane column reads
// AND conflict-free cp.async stores, no padding needed.
__device__ __forceinline__ int sw_idx(int row, int g) {
    return row * 32 + ((g ^ (row & 7)) << 2);
}

// One wavefront step s: h[i][t] for all (i,t) with t+i == s.
// h[i][t] = tanh( cur @ Wih[i]^T + hprev @ Whh[i]^T + bih[i] + bhh[i] )
// fused as [128,2048] @ [2048,1024]^T (K-concat).
__global__ void __launch_bounds__(512)
rnn_wave(int s,
         const float* __restrict__ x,
         const float* __restrict__ Wih,
         const float* __restrict__ Whh,
         const float* __restrict__ bih,
         const float* __restrict__ bhh,
         float* __restrict__ out)
{
    const int layer = blockIdx.y;
    const int t = s - layer;
    if (t < 0 || t >= TSEQ) return;

    const int mt = blockIdx.x >> 4;   // 0..1
    const int nt = blockIdx.x & 15;   // 0..15
    const int m0 = mt * MR;
    const int n0 = nt * NR;

    const float* cur = (layer == 0)
        ? (x + (size_t)t * BH)
        : (g_hbuf + (size_t)((layer-1)*2 + (t & 1)) * BH);
    const float* hprev = (t == 0) ? (const float*)0
        : (layer == NLAY-1) ? (out + (size_t)(t-1) * BH)
                            : (g_hbuf + (size_t)(layer*2 + ((t-1) & 1)) * BH);
    float* dst = (layer == NLAY-1)
        ? (out + (size_t)t * BH)
        : (g_hbuf + (size_t)(layer*2 + (t & 1)) * BH);

    const float* Wi = Wih + (size_t)layer * HID * HID;
    const float* Wh = Whh + (size_t)layer * HID * HID;

    __shared__ __align__(16) float As[2][MR*32];
    __shared__ __align__(16) float Ws[2][NR*32];

    const int tid = threadIdx.x;
    const int nthr = tid & 63;   // this thread's output column within tile
    const int my   = tid >> 6;   // m sub-row (0..7); same for all lanes of a warp -> A reads broadcast

    // Loader slot: one 16B of A and one of W per chunk.
    const int lrow = tid >> 3;   // 0..63
    const int lkq  = tid & 7;    // granule 0..7

    const unsigned sA0 = (unsigned)__cvta_generic_to_shared(&As[0][sw_idx(lrow, lkq)]);
    const unsigned sA1 = (unsigned)__cvta_generic_to_shared(&As[1][sw_idx(lrow, lkq)]);
    const unsigned sW0 = (unsigned)__cvta_generic_to_shared(&Ws[0][sw_idx(lrow, lkq)]);
    const unsigned sW1 = (unsigned)__cvta_generic_to_shared(&Ws[1][sw_idx(lrow, lkq)]);

    // t==0: h_prev is zero -> only the first HID of K.
    const int nChunks = (t == 0) ? (HID / KB) : (2 * HID / KB);

    unsigned long long acc[8];
    #pragma unroll
    for (int mi = 0; mi < 8; mi++) acc[mi] = 0ull;

    auto issue_chunk = [&](int c, int buf) {
        const int k0 = c * KB;
        const float* asrc; const float* wsrc; int koff;
        if (k0 < HID) { asrc = cur;   wsrc = Wi; koff = k0; }
        else          { asrc = hprev; wsrc = Wh; koff = k0 - HID; }
        cp_async16(buf ? sA1 : sA0, asrc + (size_t)(m0+lrow)*HID + koff + lkq*4);
        cp_async16(buf ? sW1 : sW0, wsrc + (size_t)(n0+lrow)*HID + koff + lkq*4);
        cp_commit();
    };

    auto compute_chunk = [&](int buf) {
        #pragma unroll
        for (int g = 0; g < 8; g++) {           // granule = 4 consecutive k
            // W fragment: per-lane LDS.128 (the only non-broadcast smem read)
            double2 wv = *reinterpret_cast<const double2*>(&Ws[buf][sw_idx(nthr, g)]);
            const unsigned long long w0 = __double_as_longlong(wv.x);  // (w[k],   w[k+1])
            const unsigned long long w1 = __double_as_longlong(wv.y);  // (w[k+2], w[k+3])
            // A fragments: 8 warp-broadcast LDS.128 (crossbar-free)
            unsigned long long a0[8], a1[8];
            #pragma unroll
            for (int mi = 0; mi < 8; mi++) {
                double2 av = *reinterpret_cast<const double2*>(&As[buf][sw_idx(mi*8+my, g)]);
                a0[mi] = __double_as_longlong(av.x);
                a1[mi] = __double_as_longlong(av.y);
            }
            // 16 FMA2, acc reuse distance 8 >= lat 4
            #pragma unroll
            for (int mi = 0; mi < 8; mi++) fma2(acc[mi], a0[mi], w0);
            #pragma unroll
            for (int mi = 0; mi < 8; mi++) fma2(acc[mi], a1[mi], w1);
        }
    };

    // Bias for this thread's column (loaded early, off the critical path).
    const int n = n0 + nthr;
    const float bsum = bih[layer*HID + n] + bhh[layer*HID + n];

    issue_chunk(0, 0);

    // One barrier per chunk: [wait cp(c)][bar][issue c+1][compute c].
    // The bar proves every warp finished compute(c-1), so buf (c+1)&1 (== (c-1)&1)
    // is free to overwrite; cp(c+1) then overlaps the whole compute(c).
    for (int c = 0; c < nChunks; c++) {
        cp_wait<0>();
        __syncthreads();
        if (c + 1 < nChunks) issue_chunk(c + 1, (c + 1) & 1);
        compute_chunk(c & 1);
    }

    // Epilogue: fold even/odd-K packed halves, bias, tanh, store (coalesced in n).
    #pragma unroll
    for (int mi = 0; mi < 8; mi++) {
        const int m = m0 + mi*8 + my;
        const float lo = __uint_as_float((unsigned)acc[mi]);
        const float hi = __uint_as_float((unsigned)(acc[mi] >> 32));
        dst[(size_t)m*HID + n] = tanhf(lo + hi + bsum);
    }
}

extern "C" void kernel_launch(void* const* d_in, const int* in_sizes, int n_in,
                              void* d_out, int out_size) {
    const float* x   = (const float*)d_in[0];
    const float* Wih = (const float*)d_in[1];
    const float* Whh = (const float*)d_in[2];
    const float* bih = (const float*)d_in[3];
    const float* bhh = (const float*)d_in[4];
    float* out = (float*)d_out;

    // Wavefront s = t + layer: 515 sequential launches; kernel boundaries = sync.
    const dim3 grid(32, NLAY);
    for (int s = 0; s < TSEQ + NLAY - 1; s++) {
        rnn_wave<<<grid, 512>>>(s, x, Wih, Whh, bih, bhh, out);
    }
}

// round 6
// speedup vs baseline: 3.5035x; 3.5035x over previous
#include <cuda_runtime.h>
#include <cuda_bf16.h>
#include <cstdint>

#define TSEQ  512
#define BATCH 128
#define HID   1024
#define NLAY  4
#define BH    (BATCH*HID)
#define KTOT  2048              // K = concat(cur, hprev)
#define KC    64                // K per chunk
#define NCH   (KTOT/KC)         // 32 chunks
#define TILEB 8192              // 64 rows x 128 B (bf16 KC=64)
#define STAGEB (4*TILEB)        // Ah, Al, Wh, Wl = 32 KB / stage
#define DYN_SMEM (2*STAGEB + 256)

// ---------------- static device buffers (16B-aligned for cp.async) ----------------
__device__ __align__(256) __nv_bfloat16 g_xhi[(size_t)TSEQ*BH];
__device__ __align__(256) __nv_bfloat16 g_xlo[(size_t)TSEQ*BH];
__device__ __align__(256) __nv_bfloat16 g_rhi[NLAY*2*BH];            // hidden ring hi [layer][t&1]
__device__ __align__(256) __nv_bfloat16 g_rlo[NLAY*2*BH];            // hidden ring lo
__device__ __align__(256) __nv_bfloat16 g_whi[(size_t)NLAY*HID*KTOT]; // Wcat=[W_ih;W_hh] hi, K-major
__device__ __align__(256) __nv_bfloat16 g_wlo[(size_t)NLAY*HID*KTOT];

// ---------------- PTX helpers (all baseline sm_80-level: safe on compute_103) -----
__device__ __forceinline__ unsigned smem_u32(const void* p) {
    unsigned a;
    asm("{ .reg .u64 t; cvta.to.shared.u64 t, %1; cvt.u32.u64 %0, t; }" : "=r"(a) : "l"(p));
    return a;
}
__device__ __forceinline__ void cp_async16(unsigned s, const void* g) {
    asm volatile("cp.async.ca.shared.global [%0], [%1], 16;\n" :: "r"(s), "l"(g));
}
__device__ __forceinline__ void cp_commit() { asm volatile("cp.async.commit_group;\n" ::: "memory"); }
template<int N>
__device__ __forceinline__ void cp_wait() { asm volatile("cp.async.wait_group %0;\n" :: "n"(N) : "memory"); }

__device__ __forceinline__ void ldsm4(unsigned& r0, unsigned& r1, unsigned& r2, unsigned& r3, unsigned a) {
    asm volatile("ldmatrix.sync.aligned.m8n8.x4.shared.b16 {%0,%1,%2,%3}, [%4];"
                 : "=r"(r0), "=r"(r1), "=r"(r2), "=r"(r3) : "r"(a));
}
__device__ __forceinline__ void mma16816(float4& c, unsigned a0, unsigned a1, unsigned a2, unsigned a3,
                                         unsigned b0, unsigned b1) {
    asm volatile("mma.sync.aligned.m16n8k16.row.col.f32.bf16.bf16.f32 "
                 "{%0,%1,%2,%3}, {%4,%5,%6,%7}, {%8,%9}, {%0,%1,%2,%3};"
                 : "+f"(c.x), "+f"(c.y), "+f"(c.z), "+f"(c.w)
                 : "r"(a0), "r"(a1), "r"(a2), "r"(a3), "r"(b0), "r"(b1));
}

// ---------------- split-fp32 conversion kernels ----------------
__global__ void conv_x(const float* __restrict__ x) {
    size_t i = (size_t)blockIdx.x * blockDim.x + threadIdx.x;
    if (i >= (size_t)TSEQ * BH) return;
    float v = x[i];
    __nv_bfloat16 h = __float2bfloat16(v);
    g_xhi[i] = h;
    g_xlo[i] = __float2bfloat16(v - __bfloat162float(h));
}
__global__ void conv_w(const float* __restrict__ Wih, const float* __restrict__ Whh) {
    size_t i = (size_t)blockIdx.x * blockDim.x + threadIdx.x;
    if (i >= (size_t)NLAY * HID * KTOT) return;
    int k = (int)(i & (KTOT - 1));
    size_t ln = i >> 11;                          // layer*HID + n
    float v = (k < HID) ? Wih[ln * HID + k] : Whh[ln * HID + (k - HID)];
    __nv_bfloat16 h = __float2bfloat16(v);
    g_whi[i] = h;
    g_wlo[i] = __float2bfloat16(v - __bfloat162float(h));
}

// ---------------- wavefront kernel ----------------
// h[i][t] = tanh(cur @ Wih^T + hprev @ Whh^T + b), fused K-concat GEMM,
// split-bf16 3-pass (hi*hi + hi*lo + lo*hi) on the HMMA tensor pipe.
__global__ void __launch_bounds__(256, 1)
rnn_wave_mma(int s, const float* __restrict__ bih, const float* __restrict__ bhh,
             float* __restrict__ out)
{
    const int layer = blockIdx.y;
    const int t = s - layer;
    if (t < 0 || t >= TSEQ) return;

    const int mt = blockIdx.x >> 4;        // 0..1
    const int nt = blockIdx.x & 15;        // 0..15
    const int m0 = mt * 64;
    const int n0 = nt * 64;

    extern __shared__ __align__(16) char dynsm[];
    const unsigned dbase = (smem_u32(dynsm) + 127) & ~127u;

    const int tid  = threadIdx.x;
    const int wid  = tid >> 5;
    const int lane = tid & 31;
    const int wm   = wid >> 1;             // 0..3 -> warp M offset 16*wm
    const int wn   = wid & 1;              // 0..1 -> warp N offset 32*wn

    // ---- source pointers (ring buffers; layer 3 hidden also lives in the ring) ----
    const __nv_bfloat16* curhi = (layer == 0) ? g_xhi + (size_t)t * BH
                                              : g_rhi + (size_t)((layer-1)*2 + (t & 1)) * BH;
    const __nv_bfloat16* curlo = (layer == 0) ? g_xlo + (size_t)t * BH
                                              : g_rlo + (size_t)((layer-1)*2 + (t & 1)) * BH;
    const __nv_bfloat16* phi = g_rhi + (size_t)(layer*2 + ((t-1) & 1)) * BH;
    const __nv_bfloat16* plo = g_rlo + (size_t)(layer*2 + ((t-1) & 1)) * BH;
    const __nv_bfloat16* whi = g_whi + (size_t)layer * HID * KTOT;
    const __nv_bfloat16* wlo = g_wlo + (size_t)layer * HID * KTOT;

    const int nChunks = (t == 0) ? (NCH / 2) : NCH;

    // ---- producer: each thread stores 2 granules per tile (Ah, Al, Wh, Wl) ----
    const int prow0 = tid >> 3;            // rows for granule idx tid and tid+256
    const int pg0   = tid & 7;
    const int prow1 = (tid + 256) >> 3;
    const int pg1   = (tid + 256) & 7;
    const unsigned so0 = (unsigned)(prow0*128 + ((pg0 ^ (prow0 & 7)) << 4));
    const unsigned so1 = (unsigned)(prow1*128 + ((pg1 ^ (prow1 & 7)) << 4));

    auto issue_chunk = [&](int c, int buf) {
        const unsigned sb = dbase + buf * STAGEB;
        const int k0 = c * KC;
        const __nv_bfloat16 *ah, *al; int koff;
        if (k0 < HID) { ah = curhi; al = curlo; koff = k0; }
        else          { ah = phi;   al = plo;   koff = k0 - HID; }
        // A tiles (rows = batch m0..m0+63, stride HID)
        cp_async16(sb + 0*TILEB + so0, ah + (size_t)(m0+prow0)*HID + koff + pg0*8);
        cp_async16(sb + 0*TILEB + so1, ah + (size_t)(m0+prow1)*HID + koff + pg1*8);
        cp_async16(sb + 1*TILEB + so0, al + (size_t)(m0+prow0)*HID + koff + pg0*8);
        cp_async16(sb + 1*TILEB + so1, al + (size_t)(m0+prow1)*HID + koff + pg1*8);
        // W tiles (rows = n0..n0+63, stride KTOT, K-concat column k0)
        cp_async16(sb + 2*TILEB + so0, whi + (size_t)(n0+prow0)*KTOT + k0 + pg0*8);
        cp_async16(sb + 2*TILEB + so1, whi + (size_t)(n0+prow1)*KTOT + k0 + pg1*8);
        cp_async16(sb + 3*TILEB + so0, wlo + (size_t)(n0+prow0)*KTOT + k0 + pg0*8);
        cp_async16(sb + 3*TILEB + so1, wlo + (size_t)(n0+prow1)*KTOT + k0 + pg1*8);
        cp_commit();
    };

    // ---- ldmatrix lane address components ----
    // A (m16k16): lanes 0-15 -> rows wr+(l&15) col-granule kk*2; lanes 16-31 -> same rows, kk*2+1
    const int arow = wm*16 + (lane & 15);
    const int asel = lane >> 4;                       // 0/1 -> +k8
    const unsigned aRowOff = (unsigned)(arow * 128);
    const int ar7 = arow & 7;
    // B (n8k16 pairs): lanes 0-7 rows nb+(l&7) g kk*2; 8-15 same rows g kk*2+1;
    //                  16-23 rows nb+8+(l&7) g kk*2; 24-31 rows +8, g kk*2+1
    const int brow_in = (lane & 7) + ((lane & 16) >> 1);   // 0..15
    const int bsel = (lane >> 3) & 1;
    const int brow0 = wn*32 + brow_in;                // pair 0: n-frags 0,1
    const int brow1 = wn*32 + 16 + brow_in;           // pair 1: n-frags 2,3
    const unsigned bRowOff0 = (unsigned)(brow0 * 128);
    const unsigned bRowOff1 = (unsigned)(brow1 * 128);
    const int br70 = brow0 & 7, br71 = brow1 & 7;

    float4 acc[4];
    #pragma unroll
    for (int i = 0; i < 4; i++) acc[i] = make_float4(0.f, 0.f, 0.f, 0.f);

    auto compute_chunk = [&](int buf) {
        const unsigned sb = dbase + buf * STAGEB;
        #pragma unroll
        for (int kk = 0; kk < 4; kk++) {              // 4 x k16 per KC=64 chunk
            const int gA = kk*2 + asel;
            const unsigned aoff = aRowOff + (unsigned)((gA ^ ar7) << 4);
            const int gB0 = kk*2 + bsel;
            const unsigned boff0 = bRowOff0 + (unsigned)((gB0 ^ br70) << 4);
            const unsigned boff1 = bRowOff1 + (unsigned)((gB0 ^ br71) << 4);

            unsigned ah[4], al[4], wh[8], wl[8];
            ldsm4(ah[0], ah[1], ah[2], ah[3], sb + 0*TILEB + aoff);
            ldsm4(al[0], al[1], al[2], al[3], sb + 1*TILEB + aoff);
            ldsm4(wh[0], wh[1], wh[2], wh[3], sb + 2*TILEB + boff0);
            ldsm4(wh[4], wh[5], wh[6], wh[7], sb + 2*TILEB + boff1);
            ldsm4(wl[0], wl[1], wl[2], wl[3], sb + 3*TILEB + boff0);
            ldsm4(wl[4], wl[5], wl[6], wl[7], sb + 3*TILEB + boff1);

            #pragma unroll
            for (int nf = 0; nf < 4; nf++)            // pass 1: hi*hi
                mma16816(acc[nf], ah[0], ah[1], ah[2], ah[3], wh[nf*2], wh[nf*2+1]);
            #pragma unroll
            for (int nf = 0; nf < 4; nf++)            // pass 2: hi*lo
                mma16816(acc[nf], ah[0], ah[1], ah[2], ah[3], wl[nf*2], wl[nf*2+1]);
            #pragma unroll
            for (int nf = 0; nf < 4; nf++)            // pass 3: lo*hi
                mma16816(acc[nf], al[0], al[1], al[2], al[3], wh[nf*2], wh[nf*2+1]);
        }
    };

    // ---- main pipeline: one barrier per chunk ----
    issue_chunk(0, 0);
    for (int c = 0; c < nChunks; c++) {
        cp_wait<0>();
        __syncthreads();                   // all warps done with buf (c-1)&1 == (c+1)&1
        if (c + 1 < nChunks) issue_chunk(c + 1, (c + 1) & 1);
        compute_chunk(c & 1);
    }

    // ---- epilogue: bias + tanh, split hi/lo to ring, fp32 to out for top layer ----
    const size_t rb = (size_t)(layer*2 + (t & 1)) * BH;
    const int mlo = m0 + wm*16 + (lane >> 2);
    #pragma unroll
    for (int nf = 0; nf < 4; nf++) {
        const int n = n0 + wn*32 + nf*8 + (lane & 3)*2;
        const float b0 = bih[layer*HID + n]     + bhh[layer*HID + n];
        const float b1 = bih[layer*HID + n + 1] + bhh[layer*HID + n + 1];
        const float v00 = tanhf(acc[nf].x + b0);
        const float v01 = tanhf(acc[nf].y + b1);
        const float v10 = tanhf(acc[nf].z + b0);
        const float v11 = tanhf(acc[nf].w + b1);

        #pragma unroll
        for (int rh = 0; rh < 2; rh++) {
            const int m = mlo + rh*8;
            const float va = rh ? v10 : v00;
            const float vb = rh ? v11 : v01;
            const __nv_bfloat16 ha = __float2bfloat16(va);
            const __nv_bfloat16 hb = __float2bfloat16(vb);
            const __nv_bfloat16 la = __float2bfloat16(va - __bfloat162float(ha));
            const __nv_bfloat16 lb = __float2bfloat16(vb - __bfloat162float(hb));
            const unsigned hpack = (unsigned)__bfloat16_as_ushort(ha) |
                                   ((unsigned)__bfloat16_as_ushort(hb) << 16);
            const unsigned lpack = (unsigned)__bfloat16_as_ushort(la) |
                                   ((unsigned)__bfloat16_as_ushort(lb) << 16);
            *reinterpret_cast<unsigned*>(&g_rhi[rb + (size_t)m*HID + n]) = hpack;
            *reinterpret_cast<unsigned*>(&g_rlo[rb + (size_t)m*HID + n]) = lpack;
            if (layer == NLAY - 1) {
                float2 o = make_float2(va, vb);
                *reinterpret_cast<float2*>(&out[(size_t)t*BH + (size_t)m*HID + n]) = o;
            }
        }
    }
}

extern "C" void kernel_launch(void* const* d_in, const int* in_sizes, int n_in,
                              void* d_out, int out_size) {
    const float* x   = (const float*)d_in[0];
    const float* Wih = (const float*)d_in[1];
    const float* Whh = (const float*)d_in[2];
    const float* bih = (const float*)d_in[3];
    const float* bhh = (const float*)d_in[4];
    float* out = (float*)d_out;

    cudaFuncSetAttribute(rnn_wave_mma, cudaFuncAttributeMaxDynamicSharedMemorySize, DYN_SMEM);

    // One-time (per replay) split fp32 -> bf16 hi/lo
    conv_x<<<(unsigned)(((size_t)TSEQ*BH + 255) / 256), 256>>>(x);
    conv_w<<<(unsigned)(((size_t)NLAY*HID*KTOT + 255) / 256), 256>>>(Wih, Whh);

    // Wavefront s = t + layer: 515 sequential launches; kernel boundaries = sync.
    const dim3 grid(32, NLAY);
    for (int s = 0; s < TSEQ + NLAY - 1; s++) {
        rnn_wave_mma<<<grid, 256, DYN_SMEM>>>(s, bih, bhh, out);
    }
}

// round 8
// speedup vs baseline: 3.9558x; 1.1291x over previous
#include <cuda_runtime.h>
#include <cuda_bf16.h>
#include <cstdint>

#define TSEQ  512
#define BATCH 128
#define HID   1024
#define NLAY  4
#define BH    (BATCH*HID)
#define KTOT  2048              // K = concat(cur, hprev)
#define KC    64                // K per chunk
#define NCH   (KTOT/KC)         // 32 chunks
#define TILEB 8192              // 64 rows x 128 B (bf16 KC=64)
#define STAGEB (4*TILEB)        // Ah, Al, Wh, Wl = 32 KB / stage
#define STAGES 4
#define DYN_SMEM (STAGES*STAGEB + 256)

// ---------------- static device buffers ----------------
__device__ __align__(256) __nv_bfloat16 g_xhi[(size_t)TSEQ*BH];
__device__ __align__(256) __nv_bfloat16 g_xlo[(size_t)TSEQ*BH];
__device__ __align__(256) __nv_bfloat16 g_rhi[NLAY*2*BH];             // hidden ring hi [layer][t&1]
__device__ __align__(256) __nv_bfloat16 g_rlo[NLAY*2*BH];             // hidden ring lo
__device__ __align__(256) __nv_bfloat16 g_whi[(size_t)NLAY*HID*KTOT]; // Wcat=[W_ih;W_hh] hi, K-major
__device__ __align__(256) __nv_bfloat16 g_wlo[(size_t)NLAY*HID*KTOT];

// ---------------- PTX helpers (baseline sm_80-level: safe on compute_103) -----
__device__ __forceinline__ unsigned smem_u32(const void* p) {
    unsigned a;
    asm("{ .reg .u64 t; cvta.to.shared.u64 t, %1; cvt.u32.u64 %0, t; }" : "=r"(a) : "l"(p));
    return a;
}
__device__ __forceinline__ void cp_async16(unsigned s, const void* g) {
    asm volatile("cp.async.ca.shared.global [%0], [%1], 16;\n" :: "r"(s), "l"(g));
}
__device__ __forceinline__ void cp_commit() { asm volatile("cp.async.commit_group;\n" ::: "memory"); }
template<int N>
__device__ __forceinline__ void cp_wait() { asm volatile("cp.async.wait_group %0;\n" :: "n"(N) : "memory"); }

__device__ __forceinline__ void ldsm4(unsigned& r0, unsigned& r1, unsigned& r2, unsigned& r3, unsigned a) {
    asm volatile("ldmatrix.sync.aligned.m8n8.x4.shared.b16 {%0,%1,%2,%3}, [%4];"
                 : "=r"(r0), "=r"(r1), "=r"(r2), "=r"(r3) : "r"(a));
}
__device__ __forceinline__ void mma16816(float4& c, unsigned a0, unsigned a1, unsigned a2, unsigned a3,
                                         unsigned b0, unsigned b1) {
    asm volatile("mma.sync.aligned.m16n8k16.row.col.f32.bf16.bf16.f32 "
                 "{%0,%1,%2,%3}, {%4,%5,%6,%7}, {%8,%9}, {%0,%1,%2,%3};"
                 : "+f"(c.x), "+f"(c.y), "+f"(c.z), "+f"(c.w)
                 : "r"(a0), "r"(a1), "r"(a2), "r"(a3), "r"(b0), "r"(b1));
}

// ---------------- split-fp32 conversion kernels ----------------
__global__ void conv_x(const float* __restrict__ x) {
    size_t i = (size_t)blockIdx.x * blockDim.x + threadIdx.x;
    if (i >= (size_t)TSEQ * BH) return;
    float v = x[i];
    __nv_bfloat16 h = __float2bfloat16(v);
    g_xhi[i] = h;
    g_xlo[i] = __float2bfloat16(v - __bfloat162float(h));
}
__global__ void conv_w(const float* __restrict__ Wih, const float* __restrict__ Whh) {
    size_t i = (size_t)blockIdx.x * blockDim.x + threadIdx.x;
    if (i >= (size_t)NLAY * HID * KTOT) return;
    int k = (int)(i & (KTOT - 1));
    size_t ln = i >> 11;                          // layer*HID + n
    float v = (k < HID) ? Wih[ln * HID + k] : Whh[ln * HID + (k - HID)];
    __nv_bfloat16 h = __float2bfloat16(v);
    g_whi[i] = h;
    g_wlo[i] = __float2bfloat16(v - __bfloat162float(h));
}

// ---------------- wavefront kernel ----------------
// 128 threads, 4 warps, warp-tile 32x32 (2 m-frags x 4 n-frags), CTA tile 64x64.
// Split-bf16 3-pass (hi*hi + hi*lo + lo*hi) on HMMA; 4-stage cp.async pipeline.
__global__ void __launch_bounds__(128, 1)
rnn_wave_mma(int s, const float* __restrict__ bih, const float* __restrict__ bhh,
             float* __restrict__ out)
{
    const int layer = blockIdx.y;
    const int t = s - layer;
    if (t < 0 || t >= TSEQ) return;

    const int mt = blockIdx.x >> 4;        // 0..1
    const int nt = blockIdx.x & 15;        // 0..15
    const int m0 = mt * 64;
    const int n0 = nt * 64;

    extern __shared__ __align__(16) char dynsm[];
    const unsigned dbase = (smem_u32(dynsm) + 127) & ~127u;

    const int tid  = threadIdx.x;
    const int wid  = tid >> 5;
    const int lane = tid & 31;
    const int wm   = wid >> 1;             // 0..1 -> warp M offset 32*wm
    const int wn   = wid & 1;              // 0..1 -> warp N offset 32*wn

    // ---- source pointers ----
    const __nv_bfloat16* curhi = (layer == 0) ? g_xhi + (size_t)t * BH
                                              : g_rhi + (size_t)((layer-1)*2 + (t & 1)) * BH;
    const __nv_bfloat16* curlo = (layer == 0) ? g_xlo + (size_t)t * BH
                                              : g_rlo + (size_t)((layer-1)*2 + (t & 1)) * BH;
    const __nv_bfloat16* phi = g_rhi + (size_t)(layer*2 + ((t-1) & 1)) * BH;
    const __nv_bfloat16* plo = g_rlo + (size_t)(layer*2 + ((t-1) & 1)) * BH;
    const __nv_bfloat16* whi = g_whi + (size_t)layer * HID * KTOT;
    const __nv_bfloat16* wlo = g_wlo + (size_t)layer * HID * KTOT;

    const int nChunks = (t == 0) ? (NCH / 2) : NCH;

    // ---- producer: 128 threads x 4 rows x 4 tiles; 16B granules, XOR swizzle ----
    const int prow = tid >> 3;             // 0..15
    const int pg   = tid & 7;
    const unsigned so0 = (unsigned)(prow*128 + ((pg ^ (prow & 7)) << 4));

    auto issue_chunk = [&](int c, int buf) {
        const unsigned sb = dbase + buf * STAGEB;
        const int k0 = c * KC;
        const __nv_bfloat16 *ah, *al; int koff;
        if (k0 < HID) { ah = curhi; al = curlo; koff = k0; }
        else          { ah = phi;   al = plo;   koff = k0 - HID; }
        #pragma unroll
        for (int i = 0; i < 4; i++) {
            const int row = prow + 16*i;
            const unsigned so = so0 + 2048u*i;
            cp_async16(sb + 0*TILEB + so, ah  + (size_t)(m0+row)*HID + koff + pg*8);
            cp_async16(sb + 1*TILEB + so, al  + (size_t)(m0+row)*HID + koff + pg*8);
            cp_async16(sb + 2*TILEB + so, whi + (size_t)(n0+row)*KTOT + k0 + pg*8);
            cp_async16(sb + 3*TILEB + so, wlo + (size_t)(n0+row)*KTOT + k0 + pg*8);
        }
        cp_commit();
    };

    // ---- ldmatrix lane addressing (all row bases are multiples of 8 -> XOR base = lane&7) ----
    const int x7 = lane & 7;
    const int asel = lane >> 4;                    // A k8 select
    const unsigned aRowOff0 = (unsigned)((wm*32 +      (lane & 15)) * 128);
    const unsigned aRowOff1 = (unsigned)((wm*32 + 16 + (lane & 15)) * 128);
    const int brow_in = (lane & 7) + ((lane & 16) >> 1);   // 0..15
    const int bsel = (lane >> 3) & 1;              // B k8 select
    const unsigned bRowOff0 = (unsigned)((wn*32 +      brow_in) * 128);
    const unsigned bRowOff1 = (unsigned)((wn*32 + 16 + brow_in) * 128);

    float4 acc[2][4];
    #pragma unroll
    for (int mi = 0; mi < 2; mi++)
        #pragma unroll
        for (int nf = 0; nf < 4; nf++) acc[mi][nf] = make_float4(0.f, 0.f, 0.f, 0.f);

    auto compute_chunk = [&](int buf) {
        const unsigned sb = dbase + buf * STAGEB;
        #pragma unroll
        for (int kk = 0; kk < 4; kk++) {           // 4 x k16 per KC=64 chunk
            const unsigned axor = (unsigned)(((kk*2 + asel) ^ x7) << 4);
            const unsigned bxor = (unsigned)(((kk*2 + bsel) ^ x7) << 4);
            unsigned ah[2][4], al[2][4], wh[2][4], wl[2][4];
            ldsm4(ah[0][0], ah[0][1], ah[0][2], ah[0][3], sb + 0*TILEB + aRowOff0 + axor);
            ldsm4(ah[1][0], ah[1][1], ah[1][2], ah[1][3], sb + 0*TILEB + aRowOff1 + axor);
            ldsm4(al[0][0], al[0][1], al[0][2], al[0][3], sb + 1*TILEB + aRowOff0 + axor);
            ldsm4(al[1][0], al[1][1], al[1][2], al[1][3], sb + 1*TILEB + aRowOff1 + axor);
            ldsm4(wh[0][0], wh[0][1], wh[0][2], wh[0][3], sb + 2*TILEB + bRowOff0 + bxor);
            ldsm4(wh[1][0], wh[1][1], wh[1][2], wh[1][3], sb + 2*TILEB + bRowOff1 + bxor);
            ldsm4(wl[0][0], wl[0][1], wl[0][2], wl[0][3], sb + 3*TILEB + bRowOff0 + bxor);
            ldsm4(wl[1][0], wl[1][1], wl[1][2], wl[1][3], sb + 3*TILEB + bRowOff1 + bxor);

            #pragma unroll
            for (int mi = 0; mi < 2; mi++)         // pass 1: hi*hi
                #pragma unroll
                for (int nf = 0; nf < 4; nf++)
                    mma16816(acc[mi][nf], ah[mi][0], ah[mi][1], ah[mi][2], ah[mi][3],
                             wh[nf>>1][(nf&1)*2], wh[nf>>1][(nf&1)*2+1]);
            #pragma unroll
            for (int mi = 0; mi < 2; mi++)         // pass 2: hi*lo
                #pragma unroll
                for (int nf = 0; nf < 4; nf++)
                    mma16816(acc[mi][nf], ah[mi][0], ah[mi][1], ah[mi][2], ah[mi][3],
                             wl[nf>>1][(nf&1)*2], wl[nf>>1][(nf&1)*2+1]);
            #pragma unroll
            for (int mi = 0; mi < 2; mi++)         // pass 3: lo*hi
                #pragma unroll
                for (int nf = 0; nf < 4; nf++)
                    mma16816(acc[mi][nf], al[mi][0], al[mi][1], al[mi][2], al[mi][3],
                             wh[nf>>1][(nf&1)*2], wh[nf>>1][(nf&1)*2+1]);
        }
    };

    // ---- 4-stage pipeline, one barrier per chunk ----
    issue_chunk(0, 0);
    issue_chunk(1, 1);
    issue_chunk(2, 2);
    for (int c = 0; c < nChunks; c++) {
        if (c + 2 < nChunks)      cp_wait<2>();    // chunk c landed (3 groups in flight max)
        else if (c + 1 < nChunks) cp_wait<1>();
        else                      cp_wait<0>();
        __syncthreads();          // chunk c visible to all; compute(c-1) done -> stage (c+3)&3 free
        if (c + 3 < nChunks) issue_chunk(c + 3, (c + 3) & 3);
        compute_chunk(c & 3);
    }

    // ---- epilogue: bias + tanh, split hi/lo to ring, fp32 to out for top layer ----
    const size_t rb = (size_t)(layer*2 + (t & 1)) * BH;
    #pragma unroll
    for (int mi = 0; mi < 2; mi++) {
        const int mlo = m0 + wm*32 + mi*16 + (lane >> 2);
        #pragma unroll
        for (int nf = 0; nf < 4; nf++) {
            const int n = n0 + wn*32 + nf*8 + (lane & 3)*2;
            const float b0 = bih[layer*HID + n]     + bhh[layer*HID + n];
            const float b1 = bih[layer*HID + n + 1] + bhh[layer*HID + n + 1];
            const float v00 = tanhf(acc[mi][nf].x + b0);
            const float v01 = tanhf(acc[mi][nf].y + b1);
            const float v10 = tanhf(acc[mi][nf].z + b0);
            const float v11 = tanhf(acc[mi][nf].w + b1);
            #pragma unroll
            for (int rh = 0; rh < 2; rh++) {
                const int m = mlo + rh*8;
                const float va = rh ? v10 : v00;
                const float vb = rh ? v11 : v01;
                const __nv_bfloat16 ha = __float2bfloat16(va);
                const __nv_bfloat16 hb = __float2bfloat16(vb);
                const __nv_bfloat16 la = __float2bfloat16(va - __bfloat162float(ha));
                const __nv_bfloat16 lb = __float2bfloat16(vb - __bfloat162float(hb));
                const unsigned hpack = (unsigned)__bfloat16_as_ushort(ha) |
                                       ((unsigned)__bfloat16_as_ushort(hb) << 16);
                const unsigned lpack = (unsigned)__bfloat16_as_ushort(la) |
                                       ((unsigned)__bfloat16_as_ushort(lb) << 16);
                *reinterpret_cast<unsigned*>(&g_rhi[rb + (size_t)m*HID + n]) = hpack;
                *reinterpret_cast<unsigned*>(&g_rlo[rb + (size_t)m*HID + n]) = lpack;
                if (layer == NLAY - 1) {
                    float2 o = make_float2(va, vb);
                    *reinterpret_cast<float2*>(&out[(size_t)t*BH + (size_t)m*HID + n]) = o;
                }
            }
        }
    }
}

extern "C" void kernel_launch(void* const* d_in, const int* in_sizes, int n_in,
                              void* d_out, int out_size) {
    const float* x   = (const float*)d_in[0];
    const float* Wih = (const float*)d_in[1];
    const float* Whh = (const float*)d_in[2];
    const float* bih = (const float*)d_in[3];
    const float* bhh = (const float*)d_in[4];
    float* out = (float*)d_out;

    cudaFuncSetAttribute(rnn_wave_mma, cudaFuncAttributeMaxDynamicSharedMemorySize, DYN_SMEM);

    // One-time (per replay) split fp32 -> bf16 hi/lo
    conv_x<<<(unsigned)(((size_t)TSEQ*BH + 255) / 256), 256>>>(x);
    conv_w<<<(unsigned)(((size_t)NLAY*HID*KTOT + 255) / 256), 256>>>(Wih, Whh);

    // Wavefront s = t + layer: 515 sequential launches; kernel boundaries = sync.
    const dim3 grid(32, NLAY);
    for (int s = 0; s < TSEQ + NLAY - 1; s++) {
        rnn_wave_mma<<<grid, 128, DYN_SMEM>>>(s, bih, bhh, out);
    }
}